// round 1
// baseline (speedup 1.0000x reference)
#include <cuda_runtime.h>

// Problem constants
#define BN   256      // batch
#define CN   1024     // channels
#define HW   169      // 13*13 spatial positions
#define GRID_W 13
#define SPLIT 8       // spatial splits per batch -> 2048 blocks
#define Z_CONST 17.079468445347132f   // exp(log(2*pi)+1) = 2*pi*e
#define EPS_CONST 1e-6f

// Scratch: per (b, moment, channel) partial sums. 256*5*1024 floats = 5 MB.
__device__ float g_acc[BN * 5 * CN];

// ---------------------------------------------------------------------------
// Kernel 0: zero the scratch accumulator and the scalar output.
// ---------------------------------------------------------------------------
__global__ void zero_kernel(float* __restrict__ out) {
    int i = blockIdx.x * blockDim.x + threadIdx.x;
    const int n = BN * 5 * CN;
    if (i < n) g_acc[i] = 0.0f;
    if (i == 0) out[0] = 0.0f;
}

// ---------------------------------------------------------------------------
// Kernel 1: streaming softmax + moment accumulation.
// grid = BN*SPLIT blocks, 256 threads. Thread t handles channels [4t, 4t+4).
// Each block covers ~21 spatial positions of one batch element.
// ---------------------------------------------------------------------------
__global__ __launch_bounds__(256) void accum_kernel(const float* __restrict__ x) {
    const int b    = blockIdx.x >> 3;        // / SPLIT
    const int sp   = blockIdx.x & (SPLIT - 1);
    const int p0   = (sp * HW) >> 3;         // * HW / SPLIT
    const int p1   = ((sp + 1) * HW) >> 3;
    const int tid  = threadIdx.x;
    const int wid  = tid >> 5;
    const int lane = tid & 31;
    const int c4   = tid << 2;

    __shared__ float red[2][8];

    // x laid out [B, 13, 13, C]; position p = h*13+w -> row base (b*HW + p)*CN
    const float4* __restrict__ xb =
        (const float4*)(x + (size_t)b * HW * CN);

    float S[4]   = {0.f, 0.f, 0.f, 0.f};
    float Sx[4]  = {0.f, 0.f, 0.f, 0.f};
    float Sy[4]  = {0.f, 0.f, 0.f, 0.f};
    float Sxx[4] = {0.f, 0.f, 0.f, 0.f};
    float Syy[4] = {0.f, 0.f, 0.f, 0.f};

    float4 cur = xb[(size_t)p0 * 256 + tid];

    for (int p = p0; p < p1; ++p) {
        // Prefetch next position (hides DRAM latency across the barrier chain)
        float4 nxt = cur;
        if (p + 1 < p1) nxt = xb[(size_t)(p + 1) * 256 + tid];

        float e0 = __expf(cur.x);
        float e1 = __expf(cur.y);
        float e2 = __expf(cur.z);
        float e3 = __expf(cur.w);

        float part = (e0 + e1) + (e2 + e3);
        part += __shfl_xor_sync(0xffffffffu, part, 16);
        part += __shfl_xor_sync(0xffffffffu, part, 8);
        part += __shfl_xor_sync(0xffffffffu, part, 4);
        part += __shfl_xor_sync(0xffffffffu, part, 2);
        part += __shfl_xor_sync(0xffffffffu, part, 1);
        if (lane == 0) red[p & 1][wid] = part;
        __syncthreads();
        const float* r = red[p & 1];
        float denom = ((r[0] + r[1]) + (r[2] + r[3]))
                    + ((r[4] + r[5]) + (r[6] + r[7]));
        // (single barrier per iter; double-buffered smem removes the 2nd one)

        float inv = __fdividef(1.0f, denom);

        int h = p / GRID_W;
        int w = p - h * GRID_W;
        float wx  = (float)(h + 1);
        float wy  = (float)(w + 1);
        float wx2 = wx * wx;
        float wy2 = wy * wy;

        float f[4];
        f[0] = e0 * inv; f[1] = e1 * inv; f[2] = e2 * inv; f[3] = e3 * inv;

#pragma unroll
        for (int j = 0; j < 4; ++j) {
            S[j]   += f[j];
            Sx[j]  = fmaf(wx,  f[j], Sx[j]);
            Sy[j]  = fmaf(wy,  f[j], Sy[j]);
            Sxx[j] = fmaf(wx2, f[j], Sxx[j]);
            Syy[j] = fmaf(wy2, f[j], Syy[j]);
        }
        cur = nxt;
    }

    // Accumulate partials into global scratch [B][5][C]
    float* gb = g_acc + (size_t)b * 5 * CN;
#pragma unroll
    for (int j = 0; j < 4; ++j) {
        atomicAdd(gb + 0 * CN + c4 + j, S[j]);
        atomicAdd(gb + 1 * CN + c4 + j, Sx[j]);
        atomicAdd(gb + 2 * CN + c4 + j, Sy[j]);
        atomicAdd(gb + 3 * CN + c4 + j, Sxx[j]);
        atomicAdd(gb + 4 * CN + c4 + j, Syy[j]);
    }
}

// ---------------------------------------------------------------------------
// Kernel 2: per-(b,c) determinant + global mean reduction.
// grid = BN blocks, 256 threads; thread handles 4 channels.
// ---------------------------------------------------------------------------
__global__ __launch_bounds__(256) void final_kernel(float* __restrict__ out) {
    const int b   = blockIdx.x;
    const int tid = threadIdx.x;
    const int c4  = tid << 2;
    const float* gb = g_acc + (size_t)b * 5 * CN;

    float Sa[4], Sxa[4], Sya[4], Sxxa[4], Syya[4];
    *(float4*)Sa   = *(const float4*)(gb + 0 * CN + c4);
    *(float4*)Sxa  = *(const float4*)(gb + 1 * CN + c4);
    *(float4*)Sya  = *(const float4*)(gb + 2 * CN + c4);
    *(float4*)Sxxa = *(const float4*)(gb + 3 * CN + c4);
    *(float4*)Syya = *(const float4*)(gb + 4 * CN + c4);

    float acc = 0.0f;
#pragma unroll
    for (int j = 0; j < 4; ++j) {
        float s     = Sa[j] + EPS_CONST;
        float inv_s = 1.0f / s;
        float mx    = Sxa[j] * inv_s;
        float my    = Sya[j] * inv_s;
        // sum((xv-mx)^2 f) = Sxx - 2 mx Sx + mx^2 S
        float xnum  = Sxxa[j] - 2.0f * mx * Sxa[j] + mx * mx * Sa[j];
        float ynum  = Syya[j] - 2.0f * my * Sya[j] + my * my * Sa[j];
        float x_var = xnum * inv_s * (1.0f / 169.0f);
        float y_var = ynum * inv_s * (1.0f / 169.0f);
        float d     = x_var + y_var;
        acc = fmaf(d * d, Z_CONST, acc);
    }

    // block reduce
    acc += __shfl_xor_sync(0xffffffffu, acc, 16);
    acc += __shfl_xor_sync(0xffffffffu, acc, 8);
    acc += __shfl_xor_sync(0xffffffffu, acc, 4);
    acc += __shfl_xor_sync(0xffffffffu, acc, 2);
    acc += __shfl_xor_sync(0xffffffffu, acc, 1);

    __shared__ float wsum[8];
    if ((tid & 31) == 0) wsum[tid >> 5] = acc;
    __syncthreads();
    if (tid == 0) {
        float t = ((wsum[0] + wsum[1]) + (wsum[2] + wsum[3]))
                + ((wsum[4] + wsum[5]) + (wsum[6] + wsum[7]));
        atomicAdd(out, t * (1.0f / (float)(BN * CN)));
    }
}

// ---------------------------------------------------------------------------
extern "C" void kernel_launch(void* const* d_in, const int* in_sizes, int n_in,
                              void* d_out, int out_size) {
    const float* x = (const float*)d_in[0];
    float* out = (float*)d_out;

    const int nz = BN * 5 * CN;
    zero_kernel<<<(nz + 255) / 256, 256>>>(out);
    accum_kernel<<<BN * SPLIT, 256>>>(x);
    final_kernel<<<BN, 256>>>(out);
}